// round 1
// baseline (speedup 1.0000x reference)
#include <cuda_runtime.h>
#include <math.h>

// ---------------------------------------------------------------------------
// Problem constants
// ---------------------------------------------------------------------------
#define BATCH 256
#define SEQ   512
#define DIN   64
#define HID   256

// Scratch (device globals; allocation APIs are forbidden)
__device__ float g_bufA[(size_t)BATCH * SEQ * HID];   // 128 MiB
__device__ float g_bufB[(size_t)BATCH * SEQ * HID];   // 128 MiB
__device__ float g_hfin[(size_t)BATCH * HID];

// ---------------------------------------------------------------------------
// Packed f32x2 helpers (Blackwell sm_100+)
// ---------------------------------------------------------------------------
__device__ __forceinline__ unsigned long long ffma2(unsigned long long a,
                                                    unsigned long long b,
                                                    unsigned long long c) {
    unsigned long long d;
    asm("fma.rn.f32x2 %0, %1, %2, %3;" : "=l"(d) : "l"(a), "l"(b), "l"(c));
    return d;
}
__device__ __forceinline__ float2 u2f(unsigned long long v) {
    float2 r;
    asm("mov.b64 {%0, %1}, %2;" : "=f"(r.x), "=f"(r.y) : "l"(v));
    return r;
}

// ---------------------------------------------------------------------------
// Persistent per-block RNN recurrence.
//   grid = 128 blocks, 512 threads. Block b owns batch rows 2b, 2b+1.
//   Thread t: output o = t>>1, K-half = t&1. 96 weights in regs, 32 in smem.
//   h double-buffered in smem; one __syncthreads per step.
//   h_t = tanh(xp[b,s,:] + h_{t-1} @ Whh^T)
// ---------------------------------------------------------------------------
__global__ __launch_bounds__(512, 1) void rnn_recur_kernel(
    const float* __restrict__ xp,      // [BATCH, SEQ, HID]
    const float* __restrict__ Whh,     // [HID, HID]
    float* __restrict__ out_seq,       // [BATCH, SEQ, HID] or nullptr
    float* __restrict__ out_final)     // [BATCH, HID] or nullptr
{
    // h storage: logical k -> k + 4*(k>=128): halves start 132 floats apart
    // so even/odd lane broadcast reads land on different banks.
    __shared__ __align__(16) float hbuf[2][2][272];
    __shared__ ulonglong2 wsm[8][512];  // 64 KB: weight pairs 48..63 per thread

    const int t    = threadIdx.x;
    const int o    = t >> 1;
    const int half = t & 1;
    const int myrow = blockIdx.x * 2 + half;   // batch row this thread finalizes

    // ---- load this thread's 128 weights: Whh[o, half*128 .. +127] ----
    const float* wrow = Whh + o * HID + half * 128;
    unsigned long long w[48];
#pragma unroll
    for (int q = 0; q < 24; q++) {
        ulonglong2 v = reinterpret_cast<const ulonglong2*>(wrow)[q];
        w[2 * q]     = v.x;
        w[2 * q + 1] = v.y;
    }
#pragma unroll
    for (int j = 0; j < 8; j++)
        wsm[j][t] = reinterpret_cast<const ulonglong2*>(wrow)[24 + j];

    // ---- zero initial h buffer ----
    for (int idx = t; idx < 2 * 272; idx += 512)
        (&hbuf[0][0][0])[idx] = 0.0f;
    __syncthreads();

    const float* myxp  = xp + (size_t)myrow * SEQ * HID + o;
    float*       myout = out_seq ? out_seq + (size_t)myrow * SEQ * HID + o
                                 : (float*)0;

    int   buf   = 0;
    float hlast = 0.0f;

    for (int s = 0; s < SEQ; s++) {
        // prefetch the precomputed input projection early (latency hidden
        // behind the ~1k-cycle dot loop below)
        float xv = __ldg(myxp + (size_t)s * HID);

        const ulonglong2* h0 =
            reinterpret_cast<const ulonglong2*>(&hbuf[buf][0][half * 132]);
        const ulonglong2* h1 =
            reinterpret_cast<const ulonglong2*>(&hbuf[buf][1][half * 132]);

        unsigned long long a0 = 0ull, a1 = 0ull;
#pragma unroll
        for (int q = 0; q < 24; q++) {          // register-resident weights
            ulonglong2 v0 = h0[q], v1 = h1[q];
            a0 = ffma2(w[2 * q],     v0.x, a0);
            a0 = ffma2(w[2 * q + 1], v0.y, a0);
            a1 = ffma2(w[2 * q],     v1.x, a1);
            a1 = ffma2(w[2 * q + 1], v1.y, a1);
        }
#pragma unroll
        for (int j = 0; j < 8; j++) {           // smem-resident weights
            ulonglong2 wv = wsm[j][t];
            ulonglong2 v0 = h0[24 + j], v1 = h1[24 + j];
            a0 = ffma2(wv.x, v0.x, a0);
            a0 = ffma2(wv.y, v0.y, a0);
            a1 = ffma2(wv.x, v1.x, a1);
            a1 = ffma2(wv.y, v1.y, a1);
        }

        float2 f0 = u2f(a0), f1 = u2f(a1);
        float  d0 = f0.x + f0.y;
        float  d1 = f1.x + f1.y;
        // combine the two K-halves held by lane pair (t, t^1)
        d0 += __shfl_xor_sync(0xffffffffu, d0, 1);
        d1 += __shfl_xor_sync(0xffffffffu, d1, 1);

        float pre = (half ? d1 : d0) + xv;
        float hn  = tanhf(pre);
        hlast = hn;

        hbuf[buf ^ 1][half][o + 4 * (o >> 7)] = hn;
        if (out_seq) myout[(size_t)s * HID] = hn;

        __syncthreads();
        buf ^= 1;
    }

    if (out_final) out_final[(size_t)myrow * HID + o] = hlast;
}

// ---------------------------------------------------------------------------
// Y[n, o] = sum_k X[n,k] * W[o,k] + ba[o] + bb[o]
//   256 threads (one per output col), 16 rows per block, K in 64-wide chunks
//   with weights in registers and X tile broadcast from smem. f32x2 FMAs.
// ---------------------------------------------------------------------------
template <int K>
__global__ __launch_bounds__(256, 2) void gemm_xwT_kernel(
    const float* __restrict__ X, const float* __restrict__ W,
    const float* __restrict__ ba, const float* __restrict__ bb,
    float* __restrict__ Y)
{
    __shared__ __align__(16) float xs[16][K];
    const int    t    = threadIdx.x;
    const size_t row0 = (size_t)blockIdx.x * 16;

    const float* Xt = X + row0 * K;
    constexpr int NV = 16 * K / 4;
#pragma unroll
    for (int idx = t; idx < NV; idx += 256)
        reinterpret_cast<float4*>(&xs[0][0])[idx] =
            reinterpret_cast<const float4*>(Xt)[idx];
    __syncthreads();

    unsigned long long acc[16];
#pragma unroll
    for (int r = 0; r < 16; r++) acc[r] = 0ull;

    const float* wrow = W + (size_t)t * K;
#pragma unroll 1
    for (int kc = 0; kc < K; kc += 64) {
        unsigned long long w[32];
#pragma unroll
        for (int q = 0; q < 16; q++) {
            ulonglong2 v = reinterpret_cast<const ulonglong2*>(wrow + kc)[q];
            w[2 * q]     = v.x;
            w[2 * q + 1] = v.y;
        }
#pragma unroll
        for (int r = 0; r < 16; r++) {
            const ulonglong2* xr =
                reinterpret_cast<const ulonglong2*>(&xs[r][kc]);
#pragma unroll
            for (int q = 0; q < 16; q++) {
                ulonglong2 xv = xr[q];
                acc[r] = ffma2(w[2 * q],     xv.x, acc[r]);
                acc[r] = ffma2(w[2 * q + 1], xv.y, acc[r]);
            }
        }
    }

    const float bsum = ba[t] + bb[t];
#pragma unroll
    for (int r = 0; r < 16; r++) {
        float2 a = u2f(acc[r]);
        Y[(row0 + r) * HID + t] = a.x + a.y + bsum;
    }
}

// ---------------------------------------------------------------------------
// out[b] = sigmoid(h2[b,:] . Wfc + bfc)   (D_OUT = 1)
// ---------------------------------------------------------------------------
__global__ void fc_sigmoid_kernel(const float* __restrict__ h2,
                                  const float* __restrict__ Wfc,
                                  const float* __restrict__ bfc,
                                  float* __restrict__ out)
{
    __shared__ float wf[HID];
    const int t = threadIdx.x;
    wf[t] = Wfc[t];
    __syncthreads();
    const float* hb = h2 + (size_t)t * HID;
    float s = 0.0f;
#pragma unroll 8
    for (int k = 0; k < HID; k++) s = fmaf(hb[k], wf[k], s);
    float z = s + bfc[0];
    out[t] = 1.0f / (1.0f + expf(-z));
}

// ---------------------------------------------------------------------------
// launch
// ---------------------------------------------------------------------------
extern "C" void kernel_launch(void* const* d_in, const int* in_sizes, int n_in,
                              void* d_out, int out_size)
{
    const float* x     = (const float*)d_in[0];
    const float* W_ih0 = (const float*)d_in[1];
    const float* W_hh0 = (const float*)d_in[2];
    const float* b_ih0 = (const float*)d_in[3];
    const float* b_hh0 = (const float*)d_in[4];
    const float* W_ih1 = (const float*)d_in[5];
    const float* W_hh1 = (const float*)d_in[6];
    const float* b_ih1 = (const float*)d_in[7];
    const float* b_hh1 = (const float*)d_in[8];
    const float* W_fc  = (const float*)d_in[9];
    const float* b_fc  = (const float*)d_in[10];
    float* out = (float*)d_out;

    float *bufA, *bufB, *hfin;
    cudaGetSymbolAddress((void**)&bufA, g_bufA);
    cudaGetSymbolAddress((void**)&bufB, g_bufB);
    cudaGetSymbolAddress((void**)&hfin, g_hfin);

    const int nrow_blocks = (BATCH * SEQ) / 16;  // 8192

    // Phase A: xp0 = x @ W_ih0^T + (b_ih0 + b_hh0)
    gemm_xwT_kernel<DIN><<<nrow_blocks, 256>>>(x, W_ih0, b_ih0, b_hh0, bufA);
    // Phase B: layer-0 recurrence -> h1 sequence
    rnn_recur_kernel<<<BATCH / 2, 512>>>(bufA, W_hh0, bufB, (float*)0);
    // Phase C: xp1 = h1 @ W_ih1^T + (b_ih1 + b_hh1)  (reuse bufA)
    gemm_xwT_kernel<HID><<<nrow_blocks, 256>>>(bufB, W_ih1, b_ih1, b_hh1, bufA);
    // Phase D: layer-1 recurrence -> final hidden state only
    rnn_recur_kernel<<<BATCH / 2, 512>>>(bufA, W_hh1, (float*)0, hfin);
    // Phase E: fc + sigmoid
    fc_sigmoid_kernel<<<1, 256>>>(hfin, W_fc, b_fc, out);
}